// round 8
// baseline (speedup 1.0000x reference)
#include <cuda_runtime.h>
#include <cuda_fp16.h>
#include <cstdint>

// Problem constants (fixed by the dataset)
#define BB   16
#define NN   4096
#define SS   1024
#define KK   32
#define DIN  64
#define DINC 67
#define DOUT 64

// k16 step ranges inside the shared operand buffers:
//   ks 0..3 : phase A (x @ W2, K=64)
//   ks 4..8 : phase B (xc @ W1, K=67 padded to 80)
#define KS_TOT 9

// Scratch (static device globals: allocation-free per harness rules)
__device__ float g_sum[(size_t)BB * NN * DOUT];   // xc@W1 + bias (+ xp if use_x)
__device__ float g_xp [(size_t)BB * NN * DOUT];   // xp = x@W2 (center subtraction)

// ---------------------------------------------------------------------------
// SMEM layout (bytes)
//   A buf: [ks][row:128][4 x uint2]  atom(row,j) = {f16x2 pair j, pair j+4}
//   B buf: [ks][n:64][4 x uint4]     atom(n,j)   = {Bh j, Bh j+4, Bl j, Bl j+4}
// swizzle: stored slot = (j&3) ^ (row&3)  -> conflict-free LDS.64/LDS.128
// ---------------------------------------------------------------------------
#define SAB   0                         // 9*128*32 = 36864
#define SBB   36864                     // 9*64*64  = 36864
#define SBIAS 73728                     // 256
#define SMEM_BYTES 73984

// fp16x2 pack: lo half = v0, hi half = v1
__device__ __forceinline__ uint32_t pack_h2(float v0, float v1) {
    __half2 h = __floats2half2_rn(v0, v1);
    return *(uint32_t*)&h;
}
// split pair into fp16 hi + fp16 residual (residual of fp32-exact subtraction)
__device__ __forceinline__ void split_pair_f16(float v0, float v1, uint32_t& hp, uint32_t& lp) {
    __half2 h = __floats2half2_rn(v0, v1);
    float h0 = __half2float(__low2half(h));
    float h1 = __half2float(__high2half(h));
    __half2 l = __floats2half2_rn(v0 - h0, v1 - h1);
    hp = *(uint32_t*)&h;
    lp = *(uint32_t*)&l;
}

// m16n8k16 fp16 MMA with fp32 accumulate, D += A*B (D aliases C)
__device__ __forceinline__ void mma16(float* d, uint32_t a0, uint32_t a1, uint32_t a2,
                                      uint32_t a3, uint32_t b0, uint32_t b1) {
    asm volatile(
        "mma.sync.aligned.m16n8k16.row.col.f32.f16.f16.f32 "
        "{%0,%1,%2,%3}, {%4,%5,%6,%7}, {%8,%9}, {%0,%1,%2,%3};"
        : "+f"(d[0]), "+f"(d[1]), "+f"(d[2]), "+f"(d[3])
        : "r"(a0), "r"(a1), "r"(a2), "r"(a3), "r"(b0), "r"(b1));
}

// GEMM phase over ks in [ks0, ks1): 2 MMAs per tile per ks (A*Bh + A*Bl),
// term-major ordering -> same-accumulator dep distance = 8.
__device__ __forceinline__ void gemm_phase(
    const uint2* abuf, const uint4* bbuf, int ks0, int ks1,
    float acc[2][4][4], const int rA[2], const int nI[4], int km)
{
    for (int ks = ks0; ks < ks1; ks++) {
        uint2 A0[2], A1[2];
        uint4 Bv[4];
        #pragma unroll
        for (int tM = 0; tM < 2; tM++) {
            int r0 = rA[tM], r1 = rA[tM] + 8;
            A0[tM] = abuf[(ks * 128 + r0) * 4 + (km ^ (r0 & 3))];
            A1[tM] = abuf[(ks * 128 + r1) * 4 + (km ^ (r1 & 3))];
        }
        #pragma unroll
        for (int tN = 0; tN < 4; tN++) {
            int n = nI[tN];
            Bv[tN] = bbuf[(ks * 64 + n) * 4 + (km ^ (n & 3))];
        }
        // term 1: A * Bh
        #pragma unroll
        for (int tM = 0; tM < 2; tM++)
            #pragma unroll
            for (int tN = 0; tN < 4; tN++)
                mma16(acc[tM][tN], A0[tM].x, A1[tM].x, A0[tM].y, A1[tM].y, Bv[tN].x, Bv[tN].y);
        // term 2: A * Bl
        #pragma unroll
        for (int tM = 0; tM < 2; tM++)
            #pragma unroll
            for (int tN = 0; tN < 4; tN++)
                mma16(acc[tM][tN], A0[tM].x, A1[tM].x, A0[tM].y, A1[tM].y, Bv[tN].z, Bv[tN].w);
    }
}

// ---------------------------------------------------------------------------
// proj_mma: per CTA computes 128 rows of g_xp and g_sum via fp16 2-term MMA.
// ---------------------------------------------------------------------------
__global__ void __launch_bounds__(256) proj_mma(
    const float* __restrict__ x, const float* __restrict__ xcm,
    const float* __restrict__ w1, const float* __restrict__ w2,
    const float* __restrict__ bias, const int* __restrict__ use_x)
{
    extern __shared__ char smem[];
    uint32_t* sA = (uint32_t*)(smem + SAB);
    uint32_t* sB = (uint32_t*)(smem + SBB);
    float*    sBias = (float*)(smem + SBIAS);

    const int tid  = threadIdx.x;
    const int wid  = tid >> 5;
    const int lane = tid & 31;
    const int ux   = use_x[0];
    const size_t base = (size_t)blockIdx.x * 128;

    // ---- stage W2 [64 n][64 k] -> B ks 0..3 (split hi/lo) ----
    for (int i = tid; i < 64 * 32; i += 256) {
        int n = i >> 5, jj32 = i & 31;
        int ks = jj32 >> 3, jj = jj32 & 7;
        int k0 = ks * 16 + 2 * jj;
        uint32_t hp, lp; split_pair_f16(w2[n * DIN + k0], w2[n * DIN + k0 + 1], hp, lp);
        int a4 = (ks * 64 + n) * 4 + ((jj & 3) ^ (n & 3));
        sB[a4 * 4 + (jj >> 2)]     = hp;
        sB[a4 * 4 + 2 + (jj >> 2)] = lp;
    }
    // ---- stage W1 [64 n][67 k -> 80] -> B ks 4..8 ----
    for (int i = tid; i < 64 * 40; i += 256) {
        int n = i / 40, jj40 = i - n * 40;
        int ksl = jj40 >> 3, jj = jj40 & 7;
        int k0 = ksl * 16 + 2 * jj;
        float v0 = (k0     < DINC) ? w1[n * DINC + k0]     : 0.0f;
        float v1 = (k0 + 1 < DINC) ? w1[n * DINC + k0 + 1] : 0.0f;
        uint32_t hp, lp; split_pair_f16(v0, v1, hp, lp);
        int ks = 4 + ksl;
        int a4 = (ks * 64 + n) * 4 + ((jj & 3) ^ (n & 3));
        sB[a4 * 4 + (jj >> 2)]     = hp;
        sB[a4 * 4 + 2 + (jj >> 2)] = lp;
    }
    if (tid < DOUT) sBias[tid] = bias[tid];
    // ---- stage x tile [128][64] -> A ks 0..3 (single fp16) ----
    if (ux) {
        const float* src = x + base * DIN;
        for (int i = tid; i < 128 * 32; i += 256) {
            int r = i >> 5, jj32 = i & 31;
            int ks = jj32 >> 3, jj = jj32 & 7;
            int k0 = ks * 16 + 2 * jj;
            uint32_t p = pack_h2(src[r * DIN + k0], src[r * DIN + k0 + 1]);
            int a2 = (ks * 128 + r) * 4 + ((jj & 3) ^ (r & 3));
            sA[a2 * 2 + (jj >> 2)] = p;
        }
    }
    // ---- stage xc tile [128][67 -> 80] -> A ks 4..8 ----
    {
        const float* src = xcm + base * DINC;
        for (int i = tid; i < 128 * 40; i += 256) {
            int r = i / 40, jj40 = i - r * 40;
            int ksl = jj40 >> 3, jj = jj40 & 7;
            int k0 = ksl * 16 + 2 * jj;
            float v0 = (k0     < DINC) ? src[r * DINC + k0]     : 0.0f;
            float v1 = (k0 + 1 < DINC) ? src[r * DINC + k0 + 1] : 0.0f;
            uint32_t p = pack_h2(v0, v1);
            int ks = 4 + ksl;
            int a2 = (ks * 128 + r) * 4 + ((jj & 3) ^ (r & 3));
            sA[a2 * 2 + (jj >> 2)] = p;
        }
    }
    __syncthreads();

    // ---- per-warp fragment coordinates (warp grid 4M x 2N; 32x32 per warp) --
    const int warpM = wid >> 1;            // 0..3
    const int warpN = wid & 1;             // 0..1
    const int km    = lane & 3;            // k-pair selector
    const int qr    = lane >> 2;           // 0..7
    int rA[2], nI[4];
    #pragma unroll
    for (int tM = 0; tM < 2; tM++) rA[tM] = warpM * 32 + tM * 16 + qr;
    #pragma unroll
    for (int tN = 0; tN < 4; tN++) nI[tN] = warpN * 32 + tN * 8 + qr;

    float acc[2][4][4];
    #pragma unroll
    for (int i = 0; i < 2; i++)
        #pragma unroll
        for (int j = 0; j < 4; j++)
            #pragma unroll
            for (int q = 0; q < 4; q++) acc[i][j][q] = 0.0f;

    const int colq = 2 * (lane & 3);

    // ---- Phase A: acc = x @ W2^T ; write g_xp ----
    if (ux) {
        gemm_phase((const uint2*)sA, (const uint4*)sB, 0, 4, acc, rA, nI, km);
        #pragma unroll
        for (int tM = 0; tM < 2; tM++) {
            int r = rA[tM];
            #pragma unroll
            for (int tN = 0; tN < 4; tN++) {
                int cc = warpN * 32 + tN * 8 + colq;
                float* p = g_xp + (base + r) * DOUT + cc;
                *(float2*)p = make_float2(acc[tM][tN][0], acc[tM][tN][1]);
                *(float2*)(p + 8 * DOUT) = make_float2(acc[tM][tN][2], acc[tM][tN][3]);
            }
        }
    }

    // ---- Phase B: acc += xc @ W1^T ; write g_sum = acc + bias ----
    gemm_phase((const uint2*)sA, (const uint4*)sB, 4, 9, acc, rA, nI, km);

    #pragma unroll
    for (int tM = 0; tM < 2; tM++) {
        int r = rA[tM];
        #pragma unroll
        for (int tN = 0; tN < 4; tN++) {
            int cc = warpN * 32 + tN * 8 + colq;
            float2 bv = *(const float2*)(sBias + cc);
            float* p = g_sum + (base + r) * DOUT + cc;
            *(float2*)p = make_float2(acc[tM][tN][0] + bv.x, acc[tM][tN][1] + bv.y);
            *(float2*)(p + 8 * DOUT) = make_float2(acc[tM][tN][2] + bv.x, acc[tM][tN][3] + bv.y);
        }
    }
}

// ---------------------------------------------------------------------------
// Pool kernel (proven R3 internals) + blk_base so it can be launched in 4
// sequential same-stream chunks (5 launches/call -> ncu -s 5 lands on proj).
// ---------------------------------------------------------------------------
__global__ void __launch_bounds__(256) pool_kernel(
    const void* __restrict__ indexes, const int* __restrict__ use_x,
    float* __restrict__ out, int blk_base)
{
    __shared__ int sidx[512];           // 16 pairs x 32 idx
    const int tid = threadIdx.x;
    const size_t blk = (size_t)(blockIdx.x + blk_base);

    // dtype detection: reads in-bounds under BOTH interpretations
    int2 v = ((const int2*)indexes)[blk * 256 + tid];
    bool pok = (v.y == (v.x < 0 ? -1 : 0));
    int is64 = __syncthreads_and(pok);

    if (is64) {
        longlong2 q = ((const longlong2*)indexes)[blk * 256 + tid];
        sidx[2 * tid]     = (int)q.x;
        sidx[2 * tid + 1] = (int)q.y;
    } else {
        sidx[2 * tid]     = v.x;
        sidx[2 * tid + 1] = v.y;
    }
    __syncthreads();

    const int grp    = tid >> 4;
    const int lane16 = tid & 15;
    const size_t p   = blk * 16 + grp;
    const int b      = (int)(p >> 10);
    const int* myidx = sidx + grp * 32;

    const float* sumb = g_sum + (size_t)b * NN * DOUT;
    const int c0 = lane16 * 4;
    const int id0 = myidx[0];

    const int ux = use_x[0];
    float4 cen = make_float4(0.f, 0.f, 0.f, 0.f);
    if (ux)
        cen = *(const float4*)(g_xp + ((size_t)b * NN + id0) * DOUT + c0);

    float4 a[8];
    #pragma unroll
    for (int q = 0; q < 8; q++) a[q] = make_float4(-3.4e38f, -3.4e38f, -3.4e38f, -3.4e38f);

    #pragma unroll
    for (int q = 0; q < 8; q++) {
        int4 iq = ((const int4*)myidx)[q];
        int j0 = iq.x < 0 ? id0 : iq.x;
        int j1 = iq.y < 0 ? id0 : iq.y;
        int j2 = iq.z < 0 ? id0 : iq.z;
        int j3 = iq.w < 0 ? id0 : iq.w;
        float4 v0 = *(const float4*)(sumb + (size_t)j0 * DOUT + c0);
        float4 v1 = *(const float4*)(sumb + (size_t)j1 * DOUT + c0);
        float4 v2 = *(const float4*)(sumb + (size_t)j2 * DOUT + c0);
        float4 v3 = *(const float4*)(sumb + (size_t)j3 * DOUT + c0);
        float4 m01, m23;
        m01.x = fmaxf(v0.x, v1.x); m01.y = fmaxf(v0.y, v1.y); m01.z = fmaxf(v0.z, v1.z); m01.w = fmaxf(v0.w, v1.w);
        m23.x = fmaxf(v2.x, v3.x); m23.y = fmaxf(v2.y, v3.y); m23.z = fmaxf(v2.z, v3.z); m23.w = fmaxf(v2.w, v3.w);
        a[q].x = fmaxf(m01.x, m23.x); a[q].y = fmaxf(m01.y, m23.y);
        a[q].z = fmaxf(m01.z, m23.z); a[q].w = fmaxf(m01.w, m23.w);
    }

    #pragma unroll
    for (int st = 4; st > 0; st >>= 1)
        #pragma unroll
        for (int q = 0; q < st; q++) {
            a[q].x = fmaxf(a[q].x, a[q + st].x);
            a[q].y = fmaxf(a[q].y, a[q + st].y);
            a[q].z = fmaxf(a[q].z, a[q + st].z);
            a[q].w = fmaxf(a[q].w, a[q + st].w);
        }

    float4 o = make_float4(a[0].x - cen.x, a[0].y - cen.y, a[0].z - cen.z, a[0].w - cen.w);
    *(float4*)(out + p * DOUT + c0) = o;
}

// ---------------------------------------------------------------------------
// Launcher: single stream; proj + 4 pool chunks (5 launches per call so
// ncu -s 5 -c 1 captures call-2's proj).
// ---------------------------------------------------------------------------
extern "C" void kernel_launch(void* const* d_in, const int* in_sizes, int n_in,
                              void* d_out, int out_size)
{
    const float* x    = (const float*)d_in[0];
    const float* xcm  = (const float*)d_in[1];
    const void*  idx  = d_in[2];
    const float* w1   = (const float*)d_in[3];
    const float* w2   = (const float*)d_in[4];
    const float* bias = (const float*)d_in[5];
    const int*   ux   = (const int*)d_in[6];

    cudaFuncSetAttribute(proj_mma, cudaFuncAttributeMaxDynamicSharedMemorySize, SMEM_BYTES);

    proj_mma<<<(BB * NN) / 128, 256, SMEM_BYTES>>>(x, xcm, w1, w2, bias, ux);
    for (int c = 0; c < 4; c++)
        pool_kernel<<<256, 256>>>(idx, ux, (float*)d_out, c * 256);
}

// round 9
// speedup vs baseline: 1.6250x; 1.6250x over previous
#include <cuda_runtime.h>
#include <cuda_fp16.h>
#include <cstdint>

// Problem constants (fixed by the dataset)
#define BB   16
#define NN   4096
#define SS   1024
#define KK   32
#define DIN  64
#define DINC 67
#define DOUT 64

// k16 step ranges inside the shared operand buffers:
//   ks 0..3 : phase A (x @ W2, K=64)
//   ks 4..8 : phase B (xc @ W1, K=67 padded to 80)

// Scratch (static device globals: allocation-free per harness rules)
__device__ float g_sum[(size_t)BB * NN * DOUT];   // xc@W1 + bias (+ xp if use_x)
__device__ float g_xp [(size_t)BB * NN * DOUT];   // xp = x@W2 (center subtraction)

// ---------------------------------------------------------------------------
// SMEM layout (bytes)
//   A buf: [ks][row:128][4 x uint2]  atom(row,j) = {f16x2 pair j, pair j+4}
//   B buf: [ks][n:64][4 x uint2]     same structure
// swizzle: stored slot = (j&3) ^ (row&3)  -> conflict-free LDS.64
// ---------------------------------------------------------------------------
#define SAB   0                         // 9*128*32 = 36864
#define SBB   36864                     // 9*64*32  = 18432
#define SBIAS 55296                     // 256
#define SMEM_BYTES 55552

// fp16x2 pack: lo half = v0, hi half = v1
__device__ __forceinline__ uint32_t pack_h2(float v0, float v1) {
    __half2 h = __floats2half2_rn(v0, v1);
    return *(uint32_t*)&h;
}

// m16n8k16 fp16 MMA with fp32 accumulate, D += A*B (D aliases C)
__device__ __forceinline__ void mma16(float* d, uint32_t a0, uint32_t a1, uint32_t a2,
                                      uint32_t a3, uint32_t b0, uint32_t b1) {
    asm volatile(
        "mma.sync.aligned.m16n8k16.row.col.f32.f16.f16.f32 "
        "{%0,%1,%2,%3}, {%4,%5,%6,%7}, {%8,%9}, {%0,%1,%2,%3};"
        : "+f"(d[0]), "+f"(d[1]), "+f"(d[2]), "+f"(d[3])
        : "r"(a0), "r"(a1), "r"(a2), "r"(a3), "r"(b0), "r"(b1));
}

// GEMM phase over ks in [ks0, ks1): 1 MMA per tile per ks; 8 independent
// accumulators per k-step -> dep distance 8.
__device__ __forceinline__ void gemm_phase(
    const uint2* abuf, const uint2* bbuf, int ks0, int ks1,
    float acc[2][4][4], const int rA[2], const int nI[4], int km)
{
    for (int ks = ks0; ks < ks1; ks++) {
        uint2 A0[2], A1[2], Bv[4];
        #pragma unroll
        for (int tM = 0; tM < 2; tM++) {
            int r0 = rA[tM], r1 = rA[tM] + 8;
            A0[tM] = abuf[(ks * 128 + r0) * 4 + (km ^ (r0 & 3))];
            A1[tM] = abuf[(ks * 128 + r1) * 4 + (km ^ (r1 & 3))];
        }
        #pragma unroll
        for (int tN = 0; tN < 4; tN++) {
            int n = nI[tN];
            Bv[tN] = bbuf[(ks * 64 + n) * 4 + (km ^ (n & 3))];
        }
        #pragma unroll
        for (int tM = 0; tM < 2; tM++)
            #pragma unroll
            for (int tN = 0; tN < 4; tN++)
                mma16(acc[tM][tN], A0[tM].x, A1[tM].x, A0[tM].y, A1[tM].y, Bv[tN].x, Bv[tN].y);
    }
}

// ---------------------------------------------------------------------------
// proj_mma: per CTA computes 128 rows of g_xp and g_sum via fp16 MMA.
// ---------------------------------------------------------------------------
__global__ void __launch_bounds__(256) proj_mma(
    const float* __restrict__ x, const float* __restrict__ xcm,
    const float* __restrict__ w1, const float* __restrict__ w2,
    const float* __restrict__ bias, const int* __restrict__ use_x)
{
    extern __shared__ char smem[];
    uint32_t* sA = (uint32_t*)(smem + SAB);
    uint32_t* sB = (uint32_t*)(smem + SBB);
    float*    sBias = (float*)(smem + SBIAS);

    const int tid  = threadIdx.x;
    const int wid  = tid >> 5;
    const int lane = tid & 31;
    const int ux   = use_x[0];
    const size_t base = (size_t)blockIdx.x * 128;

    // ---- stage W2 [64 n][64 k] -> B ks 0..3 ----
    for (int i = tid; i < 64 * 32; i += 256) {
        int n = i >> 5, jj32 = i & 31;
        int ks = jj32 >> 3, jj = jj32 & 7;
        int k0 = ks * 16 + 2 * jj;
        uint32_t p = pack_h2(w2[n * DIN + k0], w2[n * DIN + k0 + 1]);
        int a2 = (ks * 64 + n) * 4 + ((jj & 3) ^ (n & 3));
        sB[a2 * 2 + (jj >> 2)] = p;
    }
    // ---- stage W1 [64 n][67 k -> 80] -> B ks 4..8 ----
    for (int i = tid; i < 64 * 40; i += 256) {
        int n = i / 40, jj40 = i - n * 40;
        int ksl = jj40 >> 3, jj = jj40 & 7;
        int k0 = ksl * 16 + 2 * jj;
        float v0 = (k0     < DINC) ? w1[n * DINC + k0]     : 0.0f;
        float v1 = (k0 + 1 < DINC) ? w1[n * DINC + k0 + 1] : 0.0f;
        uint32_t p = pack_h2(v0, v1);
        int ks = 4 + ksl;
        int a2 = (ks * 64 + n) * 4 + ((jj & 3) ^ (n & 3));
        sB[a2 * 2 + (jj >> 2)] = p;
    }
    if (tid < DOUT) sBias[tid] = bias[tid];
    // ---- stage x tile [128][64] -> A ks 0..3 ----
    if (ux) {
        const float* src = x + base * DIN;
        for (int i = tid; i < 128 * 32; i += 256) {
            int r = i >> 5, jj32 = i & 31;
            int ks = jj32 >> 3, jj = jj32 & 7;
            int k0 = ks * 16 + 2 * jj;
            uint32_t p = pack_h2(src[r * DIN + k0], src[r * DIN + k0 + 1]);
            int a2 = (ks * 128 + r) * 4 + ((jj & 3) ^ (r & 3));
            sA[a2 * 2 + (jj >> 2)] = p;
        }
    }
    // ---- stage xc tile [128][67 -> 80] -> A ks 4..8 ----
    {
        const float* src = xcm + base * DINC;
        for (int i = tid; i < 128 * 40; i += 256) {
            int r = i / 40, jj40 = i - r * 40;
            int ksl = jj40 >> 3, jj = jj40 & 7;
            int k0 = ksl * 16 + 2 * jj;
            float v0 = (k0     < DINC) ? src[r * DINC + k0]     : 0.0f;
            float v1 = (k0 + 1 < DINC) ? src[r * DINC + k0 + 1] : 0.0f;
            uint32_t p = pack_h2(v0, v1);
            int ks = 4 + ksl;
            int a2 = (ks * 128 + r) * 4 + ((jj & 3) ^ (r & 3));
            sA[a2 * 2 + (jj >> 2)] = p;
        }
    }
    __syncthreads();

    // ---- per-warp fragment coordinates (warp grid 4M x 2N; 32x32 per warp) --
    const int warpM = wid >> 1;            // 0..3
    const int warpN = wid & 1;             // 0..1
    const int km    = lane & 3;            // k-pair selector
    const int qr    = lane >> 2;           // 0..7
    int rA[2], nI[4];
    #pragma unroll
    for (int tM = 0; tM < 2; tM++) rA[tM] = warpM * 32 + tM * 16 + qr;
    #pragma unroll
    for (int tN = 0; tN < 4; tN++) nI[tN] = warpN * 32 + tN * 8 + qr;

    float acc[2][4][4];
    #pragma unroll
    for (int i = 0; i < 2; i++)
        #pragma unroll
        for (int j = 0; j < 4; j++)
            #pragma unroll
            for (int q = 0; q < 4; q++) acc[i][j][q] = 0.0f;

    const int colq = 2 * (lane & 3);

    // ---- Phase A: acc = x @ W2^T ; write g_xp ----
    if (ux) {
        gemm_phase((const uint2*)sA, (const uint2*)sB, 0, 4, acc, rA, nI, km);
        #pragma unroll
        for (int tM = 0; tM < 2; tM++) {
            int r = rA[tM];
            #pragma unroll
            for (int tN = 0; tN < 4; tN++) {
                int cc = warpN * 32 + tN * 8 + colq;
                float* p = g_xp + (base + r) * DOUT + cc;
                *(float2*)p = make_float2(acc[tM][tN][0], acc[tM][tN][1]);
                *(float2*)(p + 8 * DOUT) = make_float2(acc[tM][tN][2], acc[tM][tN][3]);
            }
        }
    }

    // ---- Phase B: acc += xc @ W1^T ; write g_sum = acc + bias ----
    gemm_phase((const uint2*)sA, (const uint2*)sB, 4, 9, acc, rA, nI, km);

    #pragma unroll
    for (int tM = 0; tM < 2; tM++) {
        int r = rA[tM];
        #pragma unroll
        for (int tN = 0; tN < 4; tN++) {
            int cc = warpN * 32 + tN * 8 + colq;
            float2 bv = *(const float2*)(sBias + cc);
            float* p = g_sum + (base + r) * DOUT + cc;
            *(float2*)p = make_float2(acc[tM][tN][0] + bv.x, acc[tM][tN][1] + bv.y);
            *(float2*)(p + 8 * DOUT) = make_float2(acc[tM][tN][2] + bv.x, acc[tM][tN][3] + bv.y);
        }
    }
}

// ---------------------------------------------------------------------------
// Pool kernel (proven R3 version: single 1024-block launch, ~14.3us).
// ---------------------------------------------------------------------------
__global__ void __launch_bounds__(256) pool_kernel(
    const void* __restrict__ indexes, const int* __restrict__ use_x,
    float* __restrict__ out)
{
    __shared__ int sidx[512];           // 16 pairs x 32 idx
    const int tid = threadIdx.x;
    const size_t blk = blockIdx.x;      // 1024 blocks

    // dtype detection: reads in-bounds under BOTH interpretations
    int2 v = ((const int2*)indexes)[blk * 256 + tid];
    bool pok = (v.y == (v.x < 0 ? -1 : 0));
    int is64 = __syncthreads_and(pok);

    if (is64) {
        longlong2 q = ((const longlong2*)indexes)[blk * 256 + tid];
        sidx[2 * tid]     = (int)q.x;
        sidx[2 * tid + 1] = (int)q.y;
    } else {
        sidx[2 * tid]     = v.x;
        sidx[2 * tid + 1] = v.y;
    }
    __syncthreads();

    const int grp    = tid >> 4;
    const int lane16 = tid & 15;
    const size_t p   = blk * 16 + grp;
    const int b      = (int)(p >> 10);
    const int* myidx = sidx + grp * 32;

    const float* sumb = g_sum + (size_t)b * NN * DOUT;
    const int c0 = lane16 * 4;
    const int id0 = myidx[0];

    const int ux = use_x[0];
    float4 cen = make_float4(0.f, 0.f, 0.f, 0.f);
    if (ux)
        cen = *(const float4*)(g_xp + ((size_t)b * NN + id0) * DOUT + c0);

    float4 a[8];
    #pragma unroll
    for (int q = 0; q < 8; q++) a[q] = make_float4(-3.4e38f, -3.4e38f, -3.4e38f, -3.4e38f);

    #pragma unroll
    for (int q = 0; q < 8; q++) {
        int4 iq = ((const int4*)myidx)[q];
        int j0 = iq.x < 0 ? id0 : iq.x;
        int j1 = iq.y < 0 ? id0 : iq.y;
        int j2 = iq.z < 0 ? id0 : iq.z;
        int j3 = iq.w < 0 ? id0 : iq.w;
        float4 v0 = *(const float4*)(sumb + (size_t)j0 * DOUT + c0);
        float4 v1 = *(const float4*)(sumb + (size_t)j1 * DOUT + c0);
        float4 v2 = *(const float4*)(sumb + (size_t)j2 * DOUT + c0);
        float4 v3 = *(const float4*)(sumb + (size_t)j3 * DOUT + c0);
        float4 m01, m23;
        m01.x = fmaxf(v0.x, v1.x); m01.y = fmaxf(v0.y, v1.y); m01.z = fmaxf(v0.z, v1.z); m01.w = fmaxf(v0.w, v1.w);
        m23.x = fmaxf(v2.x, v3.x); m23.y = fmaxf(v2.y, v3.y); m23.z = fmaxf(v2.z, v3.z); m23.w = fmaxf(v2.w, v3.w);
        a[q].x = fmaxf(m01.x, m23.x); a[q].y = fmaxf(m01.y, m23.y);
        a[q].z = fmaxf(m01.z, m23.z); a[q].w = fmaxf(m01.w, m23.w);
    }

    #pragma unroll
    for (int st = 4; st > 0; st >>= 1)
        #pragma unroll
        for (int q = 0; q < st; q++) {
            a[q].x = fmaxf(a[q].x, a[q + st].x);
            a[q].y = fmaxf(a[q].y, a[q + st].y);
            a[q].z = fmaxf(a[q].z, a[q + st].z);
            a[q].w = fmaxf(a[q].w, a[q + st].w);
        }

    float4 o = make_float4(a[0].x - cen.x, a[0].y - cen.y, a[0].z - cen.z, a[0].w - cen.w);
    *(float4*)(out + p * DOUT + c0) = o;
}

// ---------------------------------------------------------------------------
// Launcher (single stream, 2 launches)
// ---------------------------------------------------------------------------
extern "C" void kernel_launch(void* const* d_in, const int* in_sizes, int n_in,
                              void* d_out, int out_size)
{
    const float* x    = (const float*)d_in[0];
    const float* xcm  = (const float*)d_in[1];
    const void*  idx  = d_in[2];
    const float* w1   = (const float*)d_in[3];
    const float* w2   = (const float*)d_in[4];
    const float* bias = (const float*)d_in[5];
    const int*   ux   = (const int*)d_in[6];

    cudaFuncSetAttribute(proj_mma, cudaFuncAttributeMaxDynamicSharedMemorySize, SMEM_BYTES);

    proj_mma<<<(BB * NN) / 128, 256, SMEM_BYTES>>>(x, xcm, w1, w2, bias, ux);
    pool_kernel<<<(BB * SS) / 16, 256>>>(idx, ux, (float*)d_out);
}